// round 13
// baseline (speedup 1.0000x reference)
#include <cuda_runtime.h>
#include <math_constants.h>

#define BATCH 32
#define NROWS 4096
#define HDIM  256
#define H4    (HDIM / 4)          // 64 float4 per row
#define NGRP  512
#define KIDX  16
#define NOUT_IDX (NGRP * KIDX)    // 8192
#define BM_BLOCKS 1024            // batchmax grid; MUST be <= resident capacity

// scratch: per-(row, channel) max over batch. 4 MB, alloc-free.
__device__ float4 g_bmax[NROWS * H4];
// rows referenced by idx this call (zeroed by groupmax for the next call)
__device__ unsigned char g_mask[NROWS];
// monotonic grid-barrier counter (never reset; replay-safe, deterministic)
__device__ unsigned int g_bar;

__device__ __forceinline__ void fmax4(float4& m, const float4 v) {
    m.x = fmaxf(m.x, v.x);
    m.y = fmaxf(m.y, v.y);
    m.z = fmaxf(m.z, v.z);
    m.w = fmaxf(m.w, v.w);
}

// Grid-wide barrier for a grid of exactly `nblocks` fully-resident CTAs.
// Monotonic ticket counter: all CTAs of one launch land in the same
// [k*nblocks, (k+1)*nblocks) window (launch boundaries separate windows),
// so they all spin for the same target.
__device__ __forceinline__ void grid_barrier(unsigned int nblocks) {
    __syncthreads();
    if (threadIdx.x == 0) {
        __threadfence();                          // mask stores visible first
        unsigned int old = atomicAdd(&g_bar, 1u);
        unsigned int target = (old / nblocks + 1u) * nblocks;
        while (true) {
            unsigned int v;
            asm volatile("ld.acquire.gpu.u32 %0, [%1];"
                         : "=r"(v) : "l"(&g_bar) : "memory");
            if (v >= target) break;
            __nanosleep(64);
        }
    }
    __syncthreads();
}

// Fused kernel: phase 1 builds the row mask from idx, grid barrier,
// phase 2 does the masked batch-max stream (the 128 MB read).
__global__ __launch_bounds__(256, 8) void fused_batchmax_kernel(
        const float4* __restrict__ x, const int* __restrict__ idx) {
    const int i = blockIdx.x * blockDim.x + threadIdx.x;   // 0 .. 262143

    // Phase 1: flag referenced rows (benign races, all write 1).
    if (i < NOUT_IDX) g_mask[idx[i]] = 1;

    grid_barrier(BM_BLOCKS);

    // Phase 2: bmax[a][h] = max over 32 batches, flagged rows only (~86.5%).
    const int row = i >> 6;
    if (__ldcg(&g_mask[row])) {
        const float4* p = x + i;
        float4 m = make_float4(-CUDART_INF_F, -CUDART_INF_F, -CUDART_INF_F, -CUDART_INF_F);
        #pragma unroll 8
        for (int b = 0; b < BATCH; ++b)
            fmax4(m, p[(size_t)b * (NROWS * H4)]);
        g_bmax[i] = m;
    }
    cudaTriggerProgrammaticLaunchCompletion();   // after this CTA's stores
}

// Kernel 2: out[g][h] = max over the 16 rows idx[g,k] of bmax[row][h].
// One block per group, 256 threads: 4 K-subsets x 64 chunks, smem tree-reduce.
// Also resets g_mask for the next replay.
__global__ __launch_bounds__(256) void groupmax_kernel(const int* __restrict__ idx,
                                                       float4* __restrict__ out) {
    const int g   = blockIdx.x;
    const int tid = threadIdx.x;

    cudaGridDependencySynchronize();             // fused kernel's stores done

    const int gt = g * 256 + tid;                // reset mask (blocks 0..15)
    if (gt < NROWS) g_mask[gt] = 0;

    __shared__ int sidx[KIDX];
    if (tid < KIDX) sidx[tid] = idx[g * KIDX + tid];
    __syncthreads();

    const int k4 = tid >> 6;         // 0..3 : which 4 indices
    const int c  = tid & 63;         // 0..63: float4 chunk

    float4 m = make_float4(-CUDART_INF_F, -CUDART_INF_F, -CUDART_INF_F, -CUDART_INF_F);
    #pragma unroll
    for (int k = k4 * 4; k < k4 * 4 + 4; ++k)
        fmax4(m, g_bmax[sidx[k] * H4 + c]);

    __shared__ float4 s[256];
    s[tid] = m;
    __syncthreads();

    if (k4 == 0) {
        #pragma unroll
        for (int j = 1; j < 4; ++j)
            fmax4(m, s[j * 64 + c]);
        out[g * H4 + c] = m;
    }
}

static inline void launch_pdl(void* fn, dim3 grid, dim3 block, void** args) {
    cudaLaunchConfig_t cfg = {};
    cfg.gridDim  = grid;
    cfg.blockDim = block;
    cfg.stream   = 0;
    cudaLaunchAttribute attr[1];
    attr[0].id = cudaLaunchAttributeProgrammaticStreamSerialization;
    attr[0].val.programmaticStreamSerializationAllowed = 1;
    cfg.attrs    = attr;
    cfg.numAttrs = 1;
    cudaLaunchKernelExC(&cfg, fn, args);
}

extern "C" void kernel_launch(void* const* d_in, const int* in_sizes, int n_in,
                              void* d_out, int out_size) {
    const float4* x = (const float4*)d_in[0];   // (32, 4096*256) fp32
    const int*  idx = (const int*)d_in[1];      // (512, 16) int32
    float4*     out = (float4*)d_out;           // 512*256 fp32 = 2048 float4

    {
        void* args[] = { (void*)&x, (void*)&idx };
        launch_pdl((void*)fused_batchmax_kernel, dim3(BM_BLOCKS), dim3(256), args);
    }
    {
        void* args[] = { (void*)&idx, (void*)&out };
        launch_pdl((void*)groupmax_kernel, dim3(NGRP), dim3(256), args);
    }
    (void)in_sizes; (void)n_in; (void)out_size;
}